// round 1
// baseline (speedup 1.0000x reference)
#include <cuda_runtime.h>

#define B_ 64
#define K_ 32
#define T_ 1280
#define C_ 16
#define E_ 64
#define CONV_CH_ 32
#define POOL_ 10
#define SEG_ (T_ / POOL_)        // 128
#define FEAT_ (CONV_CH_ * POOL_) // 320

// scratch for per-(b,k) warp / offset scalars (no allocation allowed)
__device__ float g_warp[B_ * K_];
__device__ float g_off[B_ * K_];

// ---------------------------------------------------------------------------
// Kernel 1: per-batch encoder. One block per batch element, 320 threads.
//   conv1d(pad=2) + bias + relu  ->  avgpool(10)  ->  linear+relu (E=64)
//   -> warp = embed @ warp_W^T + warp_b ; off likewise.
// ---------------------------------------------------------------------------
__global__ __launch_bounds__(FEAT_) void encoder_kernel(
    const float* __restrict__ x,       // [B, T, C]
    const float* __restrict__ conv_w,  // [32, 16, 5]
    const float* __restrict__ conv_b,  // [32]
    const float* __restrict__ lin_w,   // [64, 320]
    const float* __restrict__ lin_b,   // [64]
    const float* __restrict__ warp_W,  // [32, 64]
    const float* __restrict__ warp_b,  // [32]
    const float* __restrict__ off_W,   // [32, 64]
    const float* __restrict__ off_b,   // [32]
    float* __restrict__ out_warp,      // d_out + B*K*T*C
    float* __restrict__ out_off)       // d_out + B*K*T*C + B*K
{
    __shared__ float sw[CONV_CH_ * 5 * C_]; // rearranged: [o][kk][i]
    __shared__ float scb[CONV_CH_];
    __shared__ float sp[FEAT_];             // pooled features [o*10+pp]
    __shared__ float semb[E_];

    const int b   = blockIdx.x;
    const int tid = threadIdx.x;

    // stage conv weights rearranged for vectorized inner loop
    for (int idx = tid; idx < CONV_CH_ * C_ * 5; idx += FEAT_) {
        int o  = idx / (C_ * 5);
        int i  = (idx / 5) % C_;
        int kk = idx % 5;
        sw[(o * 5 + kk) * C_ + i] = conv_w[idx];
    }
    if (tid < CONV_CH_) scb[tid] = conv_b[tid];
    __syncthreads();

    // conv + relu + pool: thread -> (o, pp)
    {
        const int o  = tid / POOL_;
        const int pp = tid % POOL_;
        const int t0 = pp * SEG_;
        const float bias = scb[o];
        const float* xb = x + (size_t)b * T_ * C_;
        float acc = 0.f;
        for (int tt = 0; tt < SEG_; ++tt) {
            const int t = t0 + tt;
            float v = 0.f;
            #pragma unroll
            for (int kk = 0; kk < 5; ++kk) {
                const int ts = t + kk - 2;
                if (ts >= 0 && ts < T_) {
                    const float4* xr = (const float4*)(xb + (size_t)ts * C_);
                    const float4* wr = (const float4*)(sw + (o * 5 + kk) * C_);
                    #pragma unroll
                    for (int q = 0; q < 4; ++q) {
                        float4 xv = xr[q];
                        float4 wv = wr[q];
                        v += xv.x * wv.x + xv.y * wv.y + xv.z * wv.z + xv.w * wv.w;
                    }
                }
            }
            acc += fmaxf(v + bias, 0.f);
        }
        sp[o * POOL_ + pp] = acc * (1.f / SEG_);
    }
    __syncthreads();

    // linear -> relu -> embed
    if (tid < E_) {
        const float* wr = lin_w + (size_t)tid * FEAT_;
        float acc = lin_b[tid];
        #pragma unroll 4
        for (int j = 0; j < FEAT_; ++j) acc += wr[j] * sp[j];
        semb[tid] = fmaxf(acc, 0.f);
    }
    __syncthreads();

    // per-class warp / off scalars
    if (tid < K_) {
        const float* wW = warp_W + tid * E_;
        const float* oW = off_W + tid * E_;
        float aw = warp_b[tid];
        float ao = off_b[tid];
        #pragma unroll
        for (int e = 0; e < E_; ++e) {
            float em = semb[e];
            aw += wW[e] * em;
            ao += oW[e] * em;
        }
        const int bk = b * K_ + tid;
        g_warp[bk] = aw;
        g_off[bk]  = ao;
        out_warp[bk] = aw;
        out_off[bk]  = ao;
    }
}

// ---------------------------------------------------------------------------
// Kernel 2: warped output. One thread per float4 (c-quad) of [B,K,T,C].
//   warped = proto[k,i0]*(1-f) + proto[k,i1]*f + off[b,k]
// ---------------------------------------------------------------------------
__global__ __launch_bounds__(256) void warp_kernel(
    const float* __restrict__ proto,   // [K, T, C]
    float4* __restrict__ out)          // [B, K, T, C] as float4
{
    const unsigned tid = blockIdx.x * 256u + threadIdx.x;   // < B*K*T*4
    const unsigned c4 = tid & 3u;
    const unsigned r  = tid >> 2;          // b*K*T + k*T + t
    const unsigned t  = r % T_;
    const unsigned bk = r / T_;            // b*K + k
    const unsigned k  = bk % K_;

    const float w = g_warp[bk];
    const float o = g_off[bk];

    float idx = fminf(fmaxf((float)t - w, 0.f), (float)(T_ - 1));
    float i0f = floorf(idx);
    int   i0  = (int)i0f;
    int   i1  = min(i0 + 1, T_ - 1);
    float f   = idx - i0f;

    const float4* p0 = (const float4*)(proto + ((size_t)k * T_ + i0) * C_);
    const float4* p1 = (const float4*)(proto + ((size_t)k * T_ + i1) * C_);
    float4 a = p0[c4];
    float4 c = p1[c4];
    float4 res;
    res.x = fmaf(f, c.x - a.x, a.x) + o;
    res.y = fmaf(f, c.y - a.y, a.y) + o;
    res.z = fmaf(f, c.z - a.z, a.z) + o;
    res.w = fmaf(f, c.w - a.w, a.w) + o;
    out[tid] = res;
}

extern "C" void kernel_launch(void* const* d_in, const int* in_sizes, int n_in,
                              void* d_out, int out_size) {
    const float* x       = (const float*)d_in[0];
    const float* proto   = (const float*)d_in[1];
    const float* conv_w  = (const float*)d_in[2];
    const float* conv_b  = (const float*)d_in[3];
    const float* lin_w   = (const float*)d_in[4];
    const float* lin_b   = (const float*)d_in[5];
    const float* warp_W  = (const float*)d_in[6];
    const float* warp_b  = (const float*)d_in[7];
    const float* off_W   = (const float*)d_in[8];
    const float* off_b   = (const float*)d_in[9];

    float* out = (float*)d_out;
    const size_t warped_elems = (size_t)B_ * K_ * T_ * C_; // 41,943,040
    float* out_warp = out + warped_elems;
    float* out_off  = out_warp + (size_t)B_ * K_;

    encoder_kernel<<<B_, FEAT_>>>(x, conv_w, conv_b, lin_w, lin_b,
                                  warp_W, warp_b, off_W, off_b,
                                  out_warp, out_off);

    const unsigned total4 = (unsigned)(B_ * K_ * T_ * 4); // 10,485,760 threads
    warp_kernel<<<total4 / 256, 256>>>(proto, (float4*)out);
}

// round 5
// speedup vs baseline: 3.4157x; 3.4157x over previous
#include <cuda_runtime.h>

#define B_ 64
#define K_ 32
#define T_ 1280
#define C_ 16
#define E_ 64
#define CONV_CH_ 32
#define POOL_ 10
#define SEG_ 128                 // T_ / POOL_
#define FEAT_ 320                // CONV_CH_ * POOL_

// scratch (no allocation allowed)
__device__ float g_warp[B_ * K_];
__device__ float g_off[B_ * K_];
__device__ float g_pool[B_ * FEAT_];

// ---------------------------------------------------------------------------
// Stage 1: conv1d(pad=2)+bias+relu+avgpool(128). Block per (pp, b).
// 256 threads: tid = o*8 + sub; each thread: conv weights for channel o in
// registers, 16 consecutive t values, scalar relu-sum accumulator.
// ---------------------------------------------------------------------------
__global__ __launch_bounds__(256) void conv_pool_kernel(
    const float* __restrict__ x,       // [B, T, C]
    const float* __restrict__ conv_w,  // [32, 16, 5]
    const float* __restrict__ conv_b)  // [32]
{
    __shared__ float4 sx[SEG_ + 4][4];        // 132 rows x 16 floats
    __shared__ float  sw[CONV_CH_ * 5 * C_];  // rearranged [o][kk][i]

    const int pp  = blockIdx.x;
    const int b   = blockIdx.y;
    const int tid = threadIdx.x;

    // stage conv weights rearranged: [o][i][kk] -> [o][kk][i]
    for (int idx = tid; idx < CONV_CH_ * C_ * 5; idx += 256) {
        int o  = idx / (C_ * 5);
        int i  = (idx / 5) % C_;
        int kk = idx % 5;
        sw[(o * 5 + kk) * C_ + i] = conv_w[idx];
    }

    // stage x tile: global rows pp*128-2 .. pp*128+129, zero outside [0,T)
    {
        const float4* x4 = (const float4*)(x + (size_t)b * T_ * C_);
        for (int idx = tid; idx < (SEG_ + 4) * 4; idx += 256) {
            int r = idx >> 2;
            int q = idx & 3;
            int g = pp * SEG_ - 2 + r;
            float4 v = make_float4(0.f, 0.f, 0.f, 0.f);
            if (g >= 0 && g < T_) v = x4[g * 4 + q];
            sx[r][q] = v;
        }
    }
    __syncthreads();

    const int o   = tid >> 3;
    const int sub = tid & 7;

    // conv weights for this channel into registers
    float4 wreg[5][4];
    {
        const float4* swq = (const float4*)(sw + o * 5 * C_);
        #pragma unroll
        for (int kk = 0; kk < 5; ++kk)
            #pragma unroll
            for (int q = 0; q < 4; ++q)
                wreg[kk][q] = swq[kk * 4 + q];
    }
    const float bias = conv_b[o];

    float acc = 0.f;
    const int tbase = sub * 16;
    #pragma unroll 4
    for (int tt = 0; tt < 16; ++tt) {
        const int tr = tbase + tt;   // tile row of tap kk=0 is tr (global t-2)
        float v = 0.f;
        #pragma unroll
        for (int kk = 0; kk < 5; ++kk) {
            #pragma unroll
            for (int q = 0; q < 4; ++q) {
                float4 xv = sx[tr + kk][q];
                float4 wv = wreg[kk][q];
                v += xv.x * wv.x + xv.y * wv.y + xv.z * wv.z + xv.w * wv.w;
            }
        }
        acc += fmaxf(v + bias, 0.f);
    }

    // reduce the 8 sub-partials (consecutive lanes) within the warp
    acc += __shfl_down_sync(0xffffffffu, acc, 4, 8);
    acc += __shfl_down_sync(0xffffffffu, acc, 2, 8);
    acc += __shfl_down_sync(0xffffffffu, acc, 1, 8);
    if (sub == 0)
        g_pool[b * FEAT_ + o * POOL_ + pp] = acc * (1.f / SEG_);
}

// ---------------------------------------------------------------------------
// Stage 2: linear+relu -> embed, then per-class warp/off scalars. Block per b.
// ---------------------------------------------------------------------------
__global__ __launch_bounds__(64) void head_kernel(
    const float* __restrict__ lin_w,   // [64, 320]
    const float* __restrict__ lin_b,   // [64]
    const float* __restrict__ warp_W,  // [32, 64]
    const float* __restrict__ warp_b,  // [32]
    const float* __restrict__ off_W,   // [32, 64]
    const float* __restrict__ off_b,   // [32]
    float* __restrict__ out_warp,      // tail of d_out
    float* __restrict__ out_off)
{
    __shared__ float sp[FEAT_];
    __shared__ float semb[E_];

    const int b   = blockIdx.x;
    const int tid = threadIdx.x;

    for (int j = tid; j < FEAT_; j += 64) sp[j] = g_pool[b * FEAT_ + j];
    __syncthreads();

    {
        const float* wr = lin_w + (size_t)tid * FEAT_;
        float acc = lin_b[tid];
        #pragma unroll 8
        for (int j = 0; j < FEAT_; ++j) acc = fmaf(wr[j], sp[j], acc);
        semb[tid] = fmaxf(acc, 0.f);
    }
    __syncthreads();

    if (tid < K_) {
        const float* wW = warp_W + tid * E_;
        const float* oW = off_W + tid * E_;
        float aw = warp_b[tid];
        float ao = off_b[tid];
        #pragma unroll
        for (int e = 0; e < E_; ++e) {
            float em = semb[e];
            aw = fmaf(wW[e], em, aw);
            ao = fmaf(oW[e], em, ao);
        }
        const int bk = b * K_ + tid;
        g_warp[bk] = aw;
        g_off[bk]  = ao;
        out_warp[bk] = aw;
        out_off[bk]  = ao;
    }
}

// ---------------------------------------------------------------------------
// Stage 3: warped output. blockIdx.y = bk (uniform w/off/k per block),
// blockIdx.x = t-tile of 128. 256 threads x 2 float4 each.
// ---------------------------------------------------------------------------
__global__ __launch_bounds__(256) void warp_kernel(
    const float* __restrict__ proto,   // [K, T, C]
    float4* __restrict__ out)          // [B, K, T, C] as float4
{
    const int bk = blockIdx.y;
    const int k  = bk & (K_ - 1);
    const float w = g_warp[bk];
    const float o = g_off[bk];

    const int q  = threadIdx.x & 3;
    const int tl = threadIdx.x >> 2;           // 0..63
    const int t0 = blockIdx.x * 128;

    const float4* pk = (const float4*)(proto + (size_t)k * T_ * C_);
    float4* ob = out + ((size_t)bk * T_) * 4;

    #pragma unroll
    for (int h = 0; h < 2; ++h) {
        const int t = t0 + tl + h * 64;
        float idx = fminf(fmaxf((float)t - w, 0.f), (float)(T_ - 1));
        float i0f = floorf(idx);
        int   i0  = (int)i0f;
        int   i1  = min(i0 + 1, T_ - 1);
        float f   = idx - i0f;

        float4 a = pk[i0 * 4 + q];
        float4 c = pk[i1 * 4 + q];
        float4 res;
        res.x = fmaf(f, c.x - a.x, a.x) + o;
        res.y = fmaf(f, c.y - a.y, a.y) + o;
        res.z = fmaf(f, c.z - a.z, a.z) + o;
        res.w = fmaf(f, c.w - a.w, a.w) + o;
        ob[t * 4 + q] = res;
    }
}

extern "C" void kernel_launch(void* const* d_in, const int* in_sizes, int n_in,
                              void* d_out, int out_size) {
    const float* x       = (const float*)d_in[0];
    const float* proto   = (const float*)d_in[1];
    const float* conv_w  = (const float*)d_in[2];
    const float* conv_b  = (const float*)d_in[3];
    const float* lin_w   = (const float*)d_in[4];
    const float* lin_b   = (const float*)d_in[5];
    const float* warp_W  = (const float*)d_in[6];
    const float* warp_b  = (const float*)d_in[7];
    const float* off_W   = (const float*)d_in[8];
    const float* off_b   = (const float*)d_in[9];

    float* out = (float*)d_out;
    const size_t warped_elems = (size_t)B_ * K_ * T_ * C_; // 41,943,040
    float* out_warp = out + warped_elems;
    float* out_off  = out_warp + (size_t)B_ * K_;

    dim3 g1(POOL_, B_);
    conv_pool_kernel<<<g1, 256>>>(x, conv_w, conv_b);

    head_kernel<<<B_, 64>>>(lin_w, lin_b, warp_W, warp_b, off_W, off_b,
                            out_warp, out_off);

    dim3 g3(T_ / 128, B_ * K_);
    warp_kernel<<<g3, 256>>>(proto, (float4*)out);
}

// round 6
// speedup vs baseline: 5.4027x; 1.5817x over previous
#include <cuda_runtime.h>

#define B_ 64
#define K_ 32
#define T_ 1280
#define C_ 16
#define E_ 64
#define CONV_CH_ 32
#define POOL_ 10
#define SEG_ 128                 // T_ / POOL_
#define FEAT_ 320                // CONV_CH_ * POOL_
#define RSTRIDE_ 5               // x tile row stride in float4 (80B: conflict-free)

// scratch (no allocation allowed)
__device__ float g_warp[B_ * K_];
__device__ float g_off[B_ * K_];
__device__ float g_pool[B_ * FEAT_];

// ---------------------------------------------------------------------------
// Stage 1: conv1d(pad=2)+bias+relu+avgpool(128). Block per (pp, b).
// 256 threads: tid = o*8 + sub. sub handles t = sub + 8*tt (tt=0..15), so the
// 8 lanes of each crossbar phase read 8 CONSECUTIVE tile rows; with the 80B
// row stride those land in 8 distinct bank-quads -> conflict-free LDS.128.
// Channel o's 80 conv weights live in registers.
// ---------------------------------------------------------------------------
__global__ __launch_bounds__(256, 2) void conv_pool_kernel(
    const float* __restrict__ x,       // [B, T, C]
    const float* __restrict__ conv_w,  // [32, 16, 5]
    const float* __restrict__ conv_b)  // [32]
{
    __shared__ float4 sx4[(SEG_ + 4) * RSTRIDE_];   // 132 rows, stride 5 float4
    __shared__ float  sw[CONV_CH_ * 5 * C_];        // [o][kk][i]

    const int pp  = blockIdx.x;
    const int b   = blockIdx.y;
    const int tid = threadIdx.x;

    // stage conv weights rearranged: [o][i][kk] -> [o][kk][i]
    for (int idx = tid; idx < CONV_CH_ * C_ * 5; idx += 256) {
        int o   = idx / 80;
        int rem = idx - o * 80;
        int kk  = rem >> 4;
        int i   = rem & 15;
        sw[(o * 5 + kk) * C_ + i] = conv_w[o * 80 + i * 5 + kk];
    }

    // stage x tile: global rows pp*128-2 .. pp*128+129, zero outside [0,T)
    {
        const float4* x4 = (const float4*)(x + (size_t)b * T_ * C_);
        for (int idx = tid; idx < (SEG_ + 4) * 4; idx += 256) {
            int r = idx >> 2;
            int q = idx & 3;
            int g = pp * SEG_ - 2 + r;
            float4 v = make_float4(0.f, 0.f, 0.f, 0.f);
            if (g >= 0 && g < T_) v = x4[g * 4 + q];
            sx4[r * RSTRIDE_ + q] = v;
        }
    }
    __syncthreads();

    const int o   = tid >> 3;
    const int sub = tid & 7;

    // conv weights for this channel into registers
    float4 wreg[5][4];
    {
        const float4* swq = (const float4*)(sw + o * 5 * C_);
        #pragma unroll
        for (int kk = 0; kk < 5; ++kk)
            #pragma unroll
            for (int q = 0; q < 4; ++q)
                wreg[kk][q] = swq[kk * 4 + q];
    }
    const float bias = conv_b[o];

    float acc = 0.f;
    #pragma unroll 2
    for (int tt = 0; tt < 16; ++tt) {
        const int r0 = sub + tt * 8;    // tile row of tap kk=0
        float v0 = 0.f, v1 = 0.f, v2 = 0.f, v3 = 0.f;
        #pragma unroll
        for (int kk = 0; kk < 5; ++kk) {
            const float4* row = &sx4[(r0 + kk) * RSTRIDE_];
            float4 a0 = row[0], a1 = row[1], a2 = row[2], a3 = row[3];
            v0 = fmaf(a0.x, wreg[kk][0].x, v0); v0 = fmaf(a0.y, wreg[kk][0].y, v0);
            v0 = fmaf(a0.z, wreg[kk][0].z, v0); v0 = fmaf(a0.w, wreg[kk][0].w, v0);
            v1 = fmaf(a1.x, wreg[kk][1].x, v1); v1 = fmaf(a1.y, wreg[kk][1].y, v1);
            v1 = fmaf(a1.z, wreg[kk][1].z, v1); v1 = fmaf(a1.w, wreg[kk][1].w, v1);
            v2 = fmaf(a2.x, wreg[kk][2].x, v2); v2 = fmaf(a2.y, wreg[kk][2].y, v2);
            v2 = fmaf(a2.z, wreg[kk][2].z, v2); v2 = fmaf(a2.w, wreg[kk][2].w, v2);
            v3 = fmaf(a3.x, wreg[kk][3].x, v3); v3 = fmaf(a3.y, wreg[kk][3].y, v3);
            v3 = fmaf(a3.z, wreg[kk][3].z, v3); v3 = fmaf(a3.w, wreg[kk][3].w, v3);
        }
        acc += fmaxf((v0 + v1) + (v2 + v3) + bias, 0.f);
    }

    // reduce the 8 sub-partials (consecutive lanes) within the warp
    acc += __shfl_down_sync(0xffffffffu, acc, 4, 8);
    acc += __shfl_down_sync(0xffffffffu, acc, 2, 8);
    acc += __shfl_down_sync(0xffffffffu, acc, 1, 8);
    if (sub == 0)
        g_pool[b * FEAT_ + o * POOL_ + pp] = acc * (1.f / SEG_);
}

// ---------------------------------------------------------------------------
// Stage 2: linear+relu -> embed, then per-class warp/off scalars. Block per b.
// ---------------------------------------------------------------------------
__global__ __launch_bounds__(64) void head_kernel(
    const float* __restrict__ lin_w,   // [64, 320]
    const float* __restrict__ lin_b,   // [64]
    const float* __restrict__ warp_W,  // [32, 64]
    const float* __restrict__ warp_b,  // [32]
    const float* __restrict__ off_W,   // [32, 64]
    const float* __restrict__ off_b,   // [32]
    float* __restrict__ out_warp,      // tail of d_out
    float* __restrict__ out_off)
{
    __shared__ float sp[FEAT_];
    __shared__ float semb[E_];

    const int b   = blockIdx.x;
    const int tid = threadIdx.x;

    for (int j = tid; j < FEAT_; j += 64) sp[j] = g_pool[b * FEAT_ + j];
    __syncthreads();

    {
        const float* wr = lin_w + (size_t)tid * FEAT_;
        float acc = lin_b[tid];
        #pragma unroll 8
        for (int j = 0; j < FEAT_; ++j) acc = fmaf(wr[j], sp[j], acc);
        semb[tid] = fmaxf(acc, 0.f);
    }
    __syncthreads();

    if (tid < K_) {
        const float* wW = warp_W + tid * E_;
        const float* oW = off_W + tid * E_;
        float aw = warp_b[tid];
        float ao = off_b[tid];
        #pragma unroll
        for (int e = 0; e < E_; ++e) {
            float em = semb[e];
            aw = fmaf(wW[e], em, aw);
            ao = fmaf(oW[e], em, ao);
        }
        const int bk = b * K_ + tid;
        g_warp[bk] = aw;
        g_off[bk]  = ao;
        out_warp[bk] = aw;
        out_off[bk]  = ao;
    }
}

// ---------------------------------------------------------------------------
// Stage 3: warped output. blockIdx.y = bk (uniform w/off/k per block),
// blockIdx.x = t-tile of 128. 256 threads x 2 float4 each.
// ---------------------------------------------------------------------------
__global__ __launch_bounds__(256) void warp_kernel(
    const float* __restrict__ proto,   // [K, T, C]
    float4* __restrict__ out)          // [B, K, T, C] as float4
{
    const int bk = blockIdx.y;
    const int k  = bk & (K_ - 1);
    const float w = g_warp[bk];
    const float o = g_off[bk];

    const int q  = threadIdx.x & 3;
    const int tl = threadIdx.x >> 2;           // 0..63
    const int t0 = blockIdx.x * 128;

    const float4* pk = (const float4*)(proto + (size_t)k * T_ * C_);
    float4* ob = out + ((size_t)bk * T_) * 4;

    #pragma unroll
    for (int h = 0; h < 2; ++h) {
        const int t = t0 + tl + h * 64;
        float idx = fminf(fmaxf((float)t - w, 0.f), (float)(T_ - 1));
        float i0f = floorf(idx);
        int   i0  = (int)i0f;
        int   i1  = min(i0 + 1, T_ - 1);
        float f   = idx - i0f;

        float4 a = pk[i0 * 4 + q];
        float4 c = pk[i1 * 4 + q];
        float4 res;
        res.x = fmaf(f, c.x - a.x, a.x) + o;
        res.y = fmaf(f, c.y - a.y, a.y) + o;
        res.z = fmaf(f, c.z - a.z, a.z) + o;
        res.w = fmaf(f, c.w - a.w, a.w) + o;
        ob[t * 4 + q] = res;
    }
}

extern "C" void kernel_launch(void* const* d_in, const int* in_sizes, int n_in,
                              void* d_out, int out_size) {
    const float* x       = (const float*)d_in[0];
    const float* proto   = (const float*)d_in[1];
    const float* conv_w  = (const float*)d_in[2];
    const float* conv_b  = (const float*)d_in[3];
    const float* lin_w   = (const float*)d_in[4];
    const float* lin_b   = (const float*)d_in[5];
    const float* warp_W  = (const float*)d_in[6];
    const float* warp_b  = (const float*)d_in[7];
    const float* off_W   = (const float*)d_in[8];
    const float* off_b   = (const float*)d_in[9];

    float* out = (float*)d_out;
    const size_t warped_elems = (size_t)B_ * K_ * T_ * C_; // 41,943,040
    float* out_warp = out + warped_elems;
    float* out_off  = out_warp + (size_t)B_ * K_;

    dim3 g1(POOL_, B_);
    conv_pool_kernel<<<g1, 256>>>(x, conv_w, conv_b);

    head_kernel<<<B_, 64>>>(lin_w, lin_b, warp_W, warp_b, off_W, off_b,
                            out_warp, out_off);

    dim3 g3(T_ / 128, B_ * K_);
    warp_kernel<<<g3, 256>>>(proto, (float4*)out);
}

// round 8
// speedup vs baseline: 5.9713x; 1.1052x over previous
#include <cuda_runtime.h>

#define B_ 64
#define K_ 32
#define T_ 1280
#define C_ 16
#define E_ 64
#define CONV_CH_ 32
#define POOL_ 10
#define SEG_ 128                 // T_ / POOL_
#define FEAT_ 320                // CONV_CH_ * POOL_

// scratch (no allocation allowed)
__device__ float g_warp[B_ * K_];
__device__ float g_off[B_ * K_];
__device__ float g_pool[B_ * FEAT_];

// ---------------------------------------------------------------------------
// Stage 1: conv1d(pad=2)+bias+relu+avgpool(128). Block per (pp, b).
// 256 threads = 8 warps. Lane l = og*4+q (og=0..7, q=0..3)  ->  o == lane.
// Warp w handles t = w*16 .. w*16+15. For each t, ALL lanes read the same
// 5 tile rows (only quad q differs): 4 unique 16B addrs, 8-way broadcast ->
// conflict-free, ~16x less crossbar traffic than the previous mapping.
// Thread computes partials for its 4 og-channels over its quad (x reused x4),
// then a 2-step shfl_xor butterfly over q completes the C-sum before ReLU.
// ---------------------------------------------------------------------------
__global__ __launch_bounds__(256, 2) void conv_pool_kernel(
    const float* __restrict__ x,       // [B, T, C]
    const float* __restrict__ conv_w,  // [32, 16, 5]
    const float* __restrict__ conv_b)  // [32]
{
    __shared__ float4 sx4[(SEG_ + 4) * 4];     // 132 rows x 4 quads
    __shared__ float  sw[CONV_CH_ * 5 * C_];   // [o][kk][i]
    __shared__ float  sacc[8][CONV_CH_];       // per-warp pooled partials

    const int pp  = blockIdx.x;
    const int b   = blockIdx.y;
    const int tid = threadIdx.x;

    // stage conv weights rearranged: [o][i][kk] -> [o][kk][i]
    for (int idx = tid; idx < CONV_CH_ * C_ * 5; idx += 256) {
        int o   = idx / 80;
        int rem = idx - o * 80;
        int kk  = rem >> 4;
        int i   = rem & 15;
        sw[(o * 5 + kk) * C_ + i] = conv_w[o * 80 + i * 5 + kk];
    }

    // stage x tile: global rows pp*128-2 .. pp*128+129, zero outside [0,T)
    {
        const float4* x4 = (const float4*)(x + (size_t)b * T_ * C_);
        for (int idx = tid; idx < (SEG_ + 4) * 4; idx += 256) {
            int r = idx >> 2;
            int q = idx & 3;
            int g = pp * SEG_ - 2 + r;
            float4 v = make_float4(0.f, 0.f, 0.f, 0.f);
            if (g >= 0 && g < T_) v = x4[g * 4 + q];
            sx4[r * 4 + q] = v;
        }
    }
    __syncthreads();

    const int w    = tid >> 5;          // warp: t-range
    const int lane = tid & 31;          // == o
    const int og   = lane >> 2;
    const int q    = lane & 3;

    // weights: 4 channels (og*4+j) x 5 taps, quad q only -> 20 float4
    float4 wreg[4][5];
    {
        const float4* sw4 = (const float4*)sw;
        #pragma unroll
        for (int j = 0; j < 4; ++j)
            #pragma unroll
            for (int kk = 0; kk < 5; ++kk)
                wreg[j][kk] = sw4[((og * 4 + j) * 5 + kk) * 4 + q];
    }
    const float bias = conv_b[lane];

    float acc = 0.f;
    const int tbase = w * 16;
    #pragma unroll 2
    for (int tt = 0; tt < 16; ++tt) {
        const int r0 = tbase + tt;      // tile row of tap kk=0
        float v0 = 0.f, v1 = 0.f, v2 = 0.f, v3 = 0.f;
        #pragma unroll
        for (int kk = 0; kk < 5; ++kk) {
            float4 xv = sx4[(r0 + kk) * 4 + q];   // broadcast across og
            v0 = fmaf(xv.x, wreg[0][kk].x, v0); v0 = fmaf(xv.y, wreg[0][kk].y, v0);
            v0 = fmaf(xv.z, wreg[0][kk].z, v0); v0 = fmaf(xv.w, wreg[0][kk].w, v0);
            v1 = fmaf(xv.x, wreg[1][kk].x, v1); v1 = fmaf(xv.y, wreg[1][kk].y, v1);
            v1 = fmaf(xv.z, wreg[1][kk].z, v1); v1 = fmaf(xv.w, wreg[1][kk].w, v1);
            v2 = fmaf(xv.x, wreg[2][kk].x, v2); v2 = fmaf(xv.y, wreg[2][kk].y, v2);
            v2 = fmaf(xv.z, wreg[2][kk].z, v2); v2 = fmaf(xv.w, wreg[2][kk].w, v2);
            v3 = fmaf(xv.x, wreg[3][kk].x, v3); v3 = fmaf(xv.y, wreg[3][kk].y, v3);
            v3 = fmaf(xv.z, wreg[3][kk].z, v3); v3 = fmaf(xv.w, wreg[3][kk].w, v3);
        }
        // complete C-sum across the 4 q-lanes (same og)
        v0 += __shfl_xor_sync(0xffffffffu, v0, 1);
        v0 += __shfl_xor_sync(0xffffffffu, v0, 2);
        v1 += __shfl_xor_sync(0xffffffffu, v1, 1);
        v1 += __shfl_xor_sync(0xffffffffu, v1, 2);
        v2 += __shfl_xor_sync(0xffffffffu, v2, 1);
        v2 += __shfl_xor_sync(0xffffffffu, v2, 2);
        v3 += __shfl_xor_sync(0xffffffffu, v3, 1);
        v3 += __shfl_xor_sync(0xffffffffu, v3, 2);
        float vf = (q == 0) ? v0 : (q == 1) ? v1 : (q == 2) ? v2 : v3;
        acc += fmaxf(vf + bias, 0.f);
    }

    // cross-warp reduction: warp w covered t in [w*16, w*16+16)
    sacc[w][lane] = acc;
    __syncthreads();
    if (tid < CONV_CH_) {
        float s = 0.f;
        #pragma unroll
        for (int ww = 0; ww < 8; ++ww) s += sacc[ww][tid];
        g_pool[b * FEAT_ + tid * POOL_ + pp] = s * (1.f / SEG_);
    }
}

// ---------------------------------------------------------------------------
// Stage 2: linear+relu -> embed, then per-class warp/off scalars. Block per b.
// ---------------------------------------------------------------------------
__global__ __launch_bounds__(64) void head_kernel(
    const float* __restrict__ lin_w,   // [64, 320]
    const float* __restrict__ lin_b,   // [64]
    const float* __restrict__ warp_W,  // [32, 64]
    const float* __restrict__ warp_b,  // [32]
    const float* __restrict__ off_W,   // [32, 64]
    const float* __restrict__ off_b,   // [32]
    float* __restrict__ out_warp,      // tail of d_out
    float* __restrict__ out_off)
{
    __shared__ float sp[FEAT_];
    __shared__ float semb[E_];

    const int b   = blockIdx.x;
    const int tid = threadIdx.x;

    for (int j = tid; j < FEAT_; j += 64) sp[j] = g_pool[b * FEAT_ + j];
    __syncthreads();

    {
        const float* wr = lin_w + (size_t)tid * FEAT_;
        float acc = lin_b[tid];
        #pragma unroll 8
        for (int j = 0; j < FEAT_; ++j) acc = fmaf(wr[j], sp[j], acc);
        semb[tid] = fmaxf(acc, 0.f);
    }
    __syncthreads();

    if (tid < K_) {
        const float* wW = warp_W + tid * E_;
        const float* oW = off_W + tid * E_;
        float aw = warp_b[tid];
        float ao = off_b[tid];
        #pragma unroll
        for (int e = 0; e < E_; ++e) {
            float em = semb[e];
            aw = fmaf(wW[e], em, aw);
            ao = fmaf(oW[e], em, ao);
        }
        const int bk = b * K_ + tid;
        g_warp[bk] = aw;
        g_off[bk]  = ao;
        out_warp[bk] = aw;
        out_off[bk]  = ao;
    }
}

// ---------------------------------------------------------------------------
// Stage 3: warped output. blockIdx.y = bk (uniform w/off/k per block),
// blockIdx.x = t-tile of 128. 256 threads x 2 float4 each.
// ---------------------------------------------------------------------------
__global__ __launch_bounds__(256) void warp_kernel(
    const float* __restrict__ proto,   // [K, T, C]
    float4* __restrict__ out)          // [B, K, T, C] as float4
{
    const int bk = blockIdx.y;
    const int k  = bk & (K_ - 1);
    const float w = g_warp[bk];
    const float o = g_off[bk];

    const int q  = threadIdx.x & 3;
    const int tl = threadIdx.x >> 2;           // 0..63
    const int t0 = blockIdx.x * 128;

    const float4* pk = (const float4*)(proto + (size_t)k * T_ * C_);
    float4* ob = out + ((size_t)bk * T_) * 4;

    #pragma unroll
    for (int h = 0; h < 2; ++h) {
        const int t = t0 + tl + h * 64;
        float idx = fminf(fmaxf((float)t - w, 0.f), (float)(T_ - 1));
        float i0f = floorf(idx);
        int   i0  = (int)i0f;
        int   i1  = min(i0 + 1, T_ - 1);
        float f   = idx - i0f;

        float4 a = pk[i0 * 4 + q];
        float4 c = pk[i1 * 4 + q];
        float4 res;
        res.x = fmaf(f, c.x - a.x, a.x) + o;
        res.y = fmaf(f, c.y - a.y, a.y) + o;
        res.z = fmaf(f, c.z - a.z, a.z) + o;
        res.w = fmaf(f, c.w - a.w, a.w) + o;
        ob[t * 4 + q] = res;
    }
}

extern "C" void kernel_launch(void* const* d_in, const int* in_sizes, int n_in,
                              void* d_out, int out_size) {
    const float* x       = (const float*)d_in[0];
    const float* proto   = (const float*)d_in[1];
    const float* conv_w  = (const float*)d_in[2];
    const float* conv_b  = (const float*)d_in[3];
    const float* lin_w   = (const float*)d_in[4];
    const float* lin_b   = (const float*)d_in[5];
    const float* warp_W  = (const float*)d_in[6];
    const float* warp_b  = (const float*)d_in[7];
    const float* off_W   = (const float*)d_in[8];
    const float* off_b   = (const float*)d_in[9];

    float* out = (float*)d_out;
    const size_t warped_elems = (size_t)B_ * K_ * T_ * C_; // 41,943,040
    float* out_warp = out + warped_elems;
    float* out_off  = out_warp + (size_t)B_ * K_;

    dim3 g1(POOL_, B_);
    conv_pool_kernel<<<g1, 256>>>(x, conv_w, conv_b);

    head_kernel<<<B_, 64>>>(lin_w, lin_b, warp_W, warp_b, off_W, off_b,
                            out_warp, out_off);

    dim3 g3(T_ / 128, B_ * K_);
    warp_kernel<<<g3, 256>>>(proto, (float4*)out);
}

// round 11
// speedup vs baseline: 6.0594x; 1.0148x over previous
#include <cuda_runtime.h>

#define B_ 64
#define K_ 32
#define T_ 1280
#define C_ 16
#define E_ 64
#define CONV_CH_ 32
#define POOL_ 10
#define SEG_ 128                 // T_ / POOL_
#define FEAT_ 320                // CONV_CH_ * POOL_

// scratch (no allocation allowed)
__device__ float g_warp[B_ * K_];
__device__ float g_off[B_ * K_];
__device__ float g_pool[B_ * FEAT_];

// ---------------------------------------------------------------------------
// Stage 1: conv1d(pad=2)+bias+relu+avgpool(128). Block per (pp, b).
// 256 threads = 8 warps. Warp w: wg = w&1 -> channel half [wg*16, wg*16+16),
// tw = w>>2... tw = w>>1 -> t range [tw*32, tw*32+32).
// Lane: og = lane>>2 (0..7), q = lane&3. Thread owns channels o0=wg*16+og*2,
// o1=o0+1, quad q: 10 float4 of weights in regs (40 regs, was 80 -> 3 CTAs/SM).
// Per t: x quad broadcast across og (conflict-free), 40 FFMA, 4-shfl butterfly
// completes the C sum, relu, pooled accumulate.
// ---------------------------------------------------------------------------
__global__ __launch_bounds__(256, 3) void conv_pool_kernel(
    const float* __restrict__ x,       // [B, T, C]
    const float* __restrict__ conv_w,  // [32, 16, 5]
    const float* __restrict__ conv_b)  // [32]
{
    __shared__ float4 sx4[(SEG_ + 4) * 4];     // 132 rows x 4 quads
    __shared__ float  sw[CONV_CH_ * 5 * C_];   // [o][kk][i]
    __shared__ float  sacc[4][CONV_CH_];       // per-tw pooled partials

    const int pp  = blockIdx.x;
    const int b   = blockIdx.y;
    const int tid = threadIdx.x;

    // stage conv weights rearranged: [o][i][kk] -> [o][kk][i]
    for (int idx = tid; idx < CONV_CH_ * C_ * 5; idx += 256) {
        int o   = idx / 80;
        int rem = idx - o * 80;
        int kk  = rem >> 4;
        int i   = rem & 15;
        sw[(o * 5 + kk) * C_ + i] = conv_w[o * 80 + i * 5 + kk];
    }

    // stage x tile: global rows pp*128-2 .. pp*128+129, zero outside [0,T)
    {
        const float4* x4 = (const float4*)(x + (size_t)b * T_ * C_);
        for (int idx = tid; idx < (SEG_ + 4) * 4; idx += 256) {
            int r = idx >> 2;
            int q = idx & 3;
            int g = pp * SEG_ - 2 + r;
            float4 v = make_float4(0.f, 0.f, 0.f, 0.f);
            if (g >= 0 && g < T_) v = x4[g * 4 + q];
            sx4[r * 4 + q] = v;
        }
    }
    __syncthreads();

    const int w    = tid >> 5;
    const int wg   = w & 1;             // channel half
    const int tw   = w >> 1;            // t range (32 t's)
    const int lane = tid & 31;
    const int og   = lane >> 2;
    const int q    = lane & 3;
    const int o0   = wg * 16 + og * 2;

    // weights: 2 channels x 5 taps, quad q -> 10 float4 (40 regs)
    float4 wreg[2][5];
    {
        const float4* sw4 = (const float4*)sw;
        #pragma unroll
        for (int j = 0; j < 2; ++j)
            #pragma unroll
            for (int kk = 0; kk < 5; ++kk)
                wreg[j][kk] = sw4[((o0 + j) * 5 + kk) * 4 + q];
    }
    const float bias0 = conv_b[o0];
    const float bias1 = conv_b[o0 + 1];

    float acc0 = 0.f, acc1 = 0.f;
    const int tbase = tw * 32;
    #pragma unroll 4
    for (int tt = 0; tt < 32; ++tt) {
        const int r0 = tbase + tt;      // tile row of tap kk=0
        float v0 = 0.f, v1 = 0.f;
        #pragma unroll
        for (int kk = 0; kk < 5; ++kk) {
            float4 xv = sx4[(r0 + kk) * 4 + q];   // broadcast across og
            v0 = fmaf(xv.x, wreg[0][kk].x, v0); v0 = fmaf(xv.y, wreg[0][kk].y, v0);
            v0 = fmaf(xv.z, wreg[0][kk].z, v0); v0 = fmaf(xv.w, wreg[0][kk].w, v0);
            v1 = fmaf(xv.x, wreg[1][kk].x, v1); v1 = fmaf(xv.y, wreg[1][kk].y, v1);
            v1 = fmaf(xv.z, wreg[1][kk].z, v1); v1 = fmaf(xv.w, wreg[1][kk].w, v1);
        }
        // complete C-sum across the 4 q-lanes
        v0 += __shfl_xor_sync(0xffffffffu, v0, 1);
        v0 += __shfl_xor_sync(0xffffffffu, v0, 2);
        v1 += __shfl_xor_sync(0xffffffffu, v1, 1);
        v1 += __shfl_xor_sync(0xffffffffu, v1, 2);
        acc0 += fmaxf(v0 + bias0, 0.f);
        acc1 += fmaxf(v1 + bias1, 0.f);
    }

    if (q == 0) {
        sacc[tw][o0]     = acc0;
        sacc[tw][o0 + 1] = acc1;
    }
    __syncthreads();
    if (tid < CONV_CH_) {
        float s = sacc[0][tid] + sacc[1][tid] + sacc[2][tid] + sacc[3][tid];
        g_pool[b * FEAT_ + tid * POOL_ + pp] = s * (1.f / SEG_);
    }
}

// ---------------------------------------------------------------------------
// Stage 2: linear+relu -> embed, then per-class warp/off scalars. Block per b.
// ---------------------------------------------------------------------------
__global__ __launch_bounds__(64) void head_kernel(
    const float* __restrict__ lin_w,   // [64, 320]
    const float* __restrict__ lin_b,   // [64]
    const float* __restrict__ warp_W,  // [32, 64]
    const float* __restrict__ warp_b,  // [32]
    const float* __restrict__ off_W,   // [32, 64]
    const float* __restrict__ off_b,   // [32]
    float* __restrict__ out_warp,      // tail of d_out
    float* __restrict__ out_off)
{
    __shared__ float sp[FEAT_];
    __shared__ float semb[E_];

    const int b   = blockIdx.x;
    const int tid = threadIdx.x;

    for (int j = tid; j < FEAT_; j += 64) sp[j] = g_pool[b * FEAT_ + j];
    __syncthreads();

    {
        const float* wr = lin_w + (size_t)tid * FEAT_;
        float acc = lin_b[tid];
        #pragma unroll 8
        for (int j = 0; j < FEAT_; ++j) acc = fmaf(wr[j], sp[j], acc);
        semb[tid] = fmaxf(acc, 0.f);
    }
    __syncthreads();

    if (tid < K_) {
        const float* wW = warp_W + tid * E_;
        const float* oW = off_W + tid * E_;
        float aw = warp_b[tid];
        float ao = off_b[tid];
        #pragma unroll
        for (int e = 0; e < E_; ++e) {
            float em = semb[e];
            aw = fmaf(wW[e], em, aw);
            ao = fmaf(oW[e], em, ao);
        }
        const int bk = b * K_ + tid;
        g_warp[bk] = aw;
        g_off[bk]  = ao;
        out_warp[bk] = aw;
        out_off[bk]  = ao;
    }
}

// ---------------------------------------------------------------------------
// Stage 3: warped output. blockIdx.y = bk, blockIdx.x = t-tile of 128.
// w/off/k are block-uniform and idx(t) is monotone, so the <=130 prototype
// rows the tile touches are contiguous: stage them ONCE in smem (halves L2
// read traffic vs per-thread dual LDG), then interpolate and stream-store.
// ---------------------------------------------------------------------------
__global__ __launch_bounds__(256) void warp_kernel(
    const float* __restrict__ proto,   // [K, T, C]
    float4* __restrict__ out)          // [B, K, T, C] as float4
{
    __shared__ float4 sp[(SEG_ + 2) * 4];      // up to 130 rows x 4 quads

    const int bk = blockIdx.y;
    const int k  = bk & (K_ - 1);
    const float w = g_warp[bk];
    const float o = g_off[bk];
    const int t0 = blockIdx.x * SEG_;

    // contiguous row range for this tile
    const float idx_lo = fminf(fmaxf((float)t0 - w, 0.f), (float)(T_ - 1));
    const float idx_hi = fminf(fmaxf((float)(t0 + SEG_ - 1) - w, 0.f), (float)(T_ - 1));
    const int r_lo = (int)floorf(idx_lo);
    const int r_hi = min((int)floorf(idx_hi) + 1, T_ - 1);
    const int n4   = (r_hi - r_lo + 1) * 4;    // <= 520 float4

    const float4* pk = (const float4*)(proto + (size_t)k * T_ * C_);
    for (int i = threadIdx.x; i < n4; i += 256)
        sp[i] = pk[r_lo * 4 + i];
    __syncthreads();

    const int q  = threadIdx.x & 3;
    const int tl = threadIdx.x >> 2;           // 0..63
    float4* ob = out + ((size_t)bk * T_) * 4;

    #pragma unroll
    for (int h = 0; h < 2; ++h) {
        const int t = t0 + tl + h * 64;
        float idx = fminf(fmaxf((float)t - w, 0.f), (float)(T_ - 1));
        float i0f = floorf(idx);
        int   i0  = (int)i0f;
        int   i1  = min(i0 + 1, T_ - 1);
        float f   = idx - i0f;

        float4 a = sp[(i0 - r_lo) * 4 + q];
        float4 c = sp[(i1 - r_lo) * 4 + q];
        float4 res;
        res.x = fmaf(f, c.x - a.x, a.x) + o;
        res.y = fmaf(f, c.y - a.y, a.y) + o;
        res.z = fmaf(f, c.z - a.z, a.z) + o;
        res.w = fmaf(f, c.w - a.w, a.w) + o;
        __stcs(&ob[t * 4 + q], res);           // streaming store: keep proto in L2
    }
}

extern "C" void kernel_launch(void* const* d_in, const int* in_sizes, int n_in,
                              void* d_out, int out_size) {
    const float* x       = (const float*)d_in[0];
    const float* proto   = (const float*)d_in[1];
    const float* conv_w  = (const float*)d_in[2];
    const float* conv_b  = (const float*)d_in[3];
    const float* lin_w   = (const float*)d_in[4];
    const float* lin_b   = (const float*)d_in[5];
    const float* warp_W  = (const float*)d_in[6];
    const float* warp_b  = (const float*)d_in[7];
    const float* off_W   = (const float*)d_in[8];
    const float* off_b   = (const float*)d_in[9];

    float* out = (float*)d_out;
    const size_t warped_elems = (size_t)B_ * K_ * T_ * C_; // 41,943,040
    float* out_warp = out + warped_elems;
    float* out_off  = out_warp + (size_t)B_ * K_;

    dim3 g1(POOL_, B_);
    conv_pool_kernel<<<g1, 256>>>(x, conv_w, conv_b);

    head_kernel<<<B_, 64>>>(lin_w, lin_b, warp_W, warp_b, off_W, off_b,
                            out_warp, out_off);

    dim3 g3(T_ / SEG_, B_ * K_);
    warp_kernel<<<g3, 256>>>(proto, (float4*)out);
}

// round 13
// speedup vs baseline: 6.9224x; 1.1424x over previous
#include <cuda_runtime.h>

#define B_ 64
#define K_ 32
#define T_ 1280
#define C_ 16
#define E_ 64
#define CONV_CH_ 32
#define POOL_ 10
#define SEG_ 128                 // T_ / POOL_
#define FEAT_ 320                // CONV_CH_ * POOL_
#define WSEG_ 256                // warp_kernel t-tile

// scratch (no allocation allowed)
__device__ float g_warp[B_ * K_];
__device__ float g_off[B_ * K_];
__device__ float g_pool[B_ * FEAT_];

// ---------------------------------------------------------------------------
// Stage 1: conv1d(pad=2)+bias+relu+avgpool(128). Block per (pp, b).
// 8 warps: wg = w&1 channel half, tw = w>>1 t-range of 32.
// Lane: og=lane>>2, q=lane&3; thread owns channels o0,o0+1, quad q.
// Processes t-pairs (tt, tt+16): 4 independent FMA chains + 2 independent
// shfl groups per iteration to cover FMA/shfl latency at occ~37%.
// ---------------------------------------------------------------------------
__global__ __launch_bounds__(256, 3) void conv_pool_kernel(
    const float* __restrict__ x,       // [B, T, C]
    const float* __restrict__ conv_w,  // [32, 16, 5]
    const float* __restrict__ conv_b)  // [32]
{
    __shared__ float4 sx4[(SEG_ + 4) * 4];     // 132 rows x 4 quads
    __shared__ float  sw[CONV_CH_ * 5 * C_];   // [o][kk][i]
    __shared__ float  sacc[4][CONV_CH_];       // per-tw pooled partials

    const int pp  = blockIdx.x;
    const int b   = blockIdx.y;
    const int tid = threadIdx.x;

    // stage conv weights rearranged: [o][i][kk] -> [o][kk][i]
    for (int idx = tid; idx < CONV_CH_ * C_ * 5; idx += 256) {
        int o   = idx / 80;
        int rem = idx - o * 80;
        int kk  = rem >> 4;
        int i   = rem & 15;
        sw[(o * 5 + kk) * C_ + i] = conv_w[o * 80 + i * 5 + kk];
    }

    // stage x tile: global rows pp*128-2 .. pp*128+129, zero outside [0,T)
    {
        const float4* x4 = (const float4*)(x + (size_t)b * T_ * C_);
        for (int idx = tid; idx < (SEG_ + 4) * 4; idx += 256) {
            int r = idx >> 2;
            int q = idx & 3;
            int g = pp * SEG_ - 2 + r;
            float4 v = make_float4(0.f, 0.f, 0.f, 0.f);
            if (g >= 0 && g < T_) v = x4[g * 4 + q];
            sx4[r * 4 + q] = v;
        }
    }
    __syncthreads();

    const int w    = tid >> 5;
    const int wg   = w & 1;             // channel half
    const int tw   = w >> 1;            // t range (32 t's)
    const int lane = tid & 31;
    const int og   = lane >> 2;
    const int q    = lane & 3;
    const int o0   = wg * 16 + og * 2;

    // weights: 2 channels x 5 taps, quad q -> 10 float4 (40 regs)
    float4 wreg[2][5];
    {
        const float4* sw4 = (const float4*)sw;
        #pragma unroll
        for (int j = 0; j < 2; ++j)
            #pragma unroll
            for (int kk = 0; kk < 5; ++kk)
                wreg[j][kk] = sw4[((o0 + j) * 5 + kk) * 4 + q];
    }
    const float bias0 = conv_b[o0];
    const float bias1 = conv_b[o0 + 1];

    float acc0 = 0.f, acc1 = 0.f;
    const int tbase = tw * 32;
    #pragma unroll 2
    for (int tt = 0; tt < 16; ++tt) {
        const int ra = tbase + tt;
        const int rb = ra + 16;
        float va0 = 0.f, va1 = 0.f, vb0 = 0.f, vb1 = 0.f;
        #pragma unroll
        for (int kk = 0; kk < 5; ++kk) {
            float4 xa = sx4[(ra + kk) * 4 + q];   // broadcast across og
            float4 xb = sx4[(rb + kk) * 4 + q];
            va0 = fmaf(xa.x, wreg[0][kk].x, va0); va0 = fmaf(xa.y, wreg[0][kk].y, va0);
            va0 = fmaf(xa.z, wreg[0][kk].z, va0); va0 = fmaf(xa.w, wreg[0][kk].w, va0);
            va1 = fmaf(xa.x, wreg[1][kk].x, va1); va1 = fmaf(xa.y, wreg[1][kk].y, va1);
            va1 = fmaf(xa.z, wreg[1][kk].z, va1); va1 = fmaf(xa.w, wreg[1][kk].w, va1);
            vb0 = fmaf(xb.x, wreg[0][kk].x, vb0); vb0 = fmaf(xb.y, wreg[0][kk].y, vb0);
            vb0 = fmaf(xb.z, wreg[0][kk].z, vb0); vb0 = fmaf(xb.w, wreg[0][kk].w, vb0);
            vb1 = fmaf(xb.x, wreg[1][kk].x, vb1); vb1 = fmaf(xb.y, wreg[1][kk].y, vb1);
            vb1 = fmaf(xb.z, wreg[1][kk].z, vb1); vb1 = fmaf(xb.w, wreg[1][kk].w, vb1);
        }
        // complete C-sums across the 4 q-lanes; 4 independent shfl chains
        va0 += __shfl_xor_sync(0xffffffffu, va0, 1);
        va1 += __shfl_xor_sync(0xffffffffu, va1, 1);
        vb0 += __shfl_xor_sync(0xffffffffu, vb0, 1);
        vb1 += __shfl_xor_sync(0xffffffffu, vb1, 1);
        va0 += __shfl_xor_sync(0xffffffffu, va0, 2);
        va1 += __shfl_xor_sync(0xffffffffu, va1, 2);
        vb0 += __shfl_xor_sync(0xffffffffu, vb0, 2);
        vb1 += __shfl_xor_sync(0xffffffffu, vb1, 2);
        acc0 += fmaxf(va0 + bias0, 0.f) + fmaxf(vb0 + bias0, 0.f);
        acc1 += fmaxf(va1 + bias1, 0.f) + fmaxf(vb1 + bias1, 0.f);
    }

    if (q == 0) {
        sacc[tw][o0]     = acc0;
        sacc[tw][o0 + 1] = acc1;
    }
    __syncthreads();
    if (tid < CONV_CH_) {
        float s = sacc[0][tid] + sacc[1][tid] + sacc[2][tid] + sacc[3][tid];
        g_pool[b * FEAT_ + tid * POOL_ + pp] = s * (1.f / SEG_);
    }
}

// ---------------------------------------------------------------------------
// Stage 2: linear+relu -> embed, then per-class warp/off scalars. Block per b.
// ---------------------------------------------------------------------------
__global__ __launch_bounds__(64) void head_kernel(
    const float* __restrict__ lin_w,   // [64, 320]
    const float* __restrict__ lin_b,   // [64]
    const float* __restrict__ warp_W,  // [32, 64]
    const float* __restrict__ warp_b,  // [32]
    const float* __restrict__ off_W,   // [32, 64]
    const float* __restrict__ off_b,   // [32]
    float* __restrict__ out_warp,      // tail of d_out
    float* __restrict__ out_off)
{
    __shared__ float4 sp[FEAT_ / 4];
    __shared__ float semb[E_];

    const int b   = blockIdx.x;
    const int tid = threadIdx.x;

    {
        const float4* gp = (const float4*)(g_pool + b * FEAT_);
        for (int j = tid; j < FEAT_ / 4; j += 64) sp[j] = gp[j];
    }
    __syncthreads();

    {
        const float4* wr = (const float4*)(lin_w + (size_t)tid * FEAT_);
        float a0 = lin_b[tid], a1 = 0.f;
        #pragma unroll 4
        for (int j = 0; j < FEAT_ / 4; j += 2) {
            float4 w0 = wr[j],   p0 = sp[j];
            float4 w1 = wr[j+1], p1 = sp[j+1];
            a0 = fmaf(w0.x, p0.x, a0); a0 = fmaf(w0.y, p0.y, a0);
            a0 = fmaf(w0.z, p0.z, a0); a0 = fmaf(w0.w, p0.w, a0);
            a1 = fmaf(w1.x, p1.x, a1); a1 = fmaf(w1.y, p1.y, a1);
            a1 = fmaf(w1.z, p1.z, a1); a1 = fmaf(w1.w, p1.w, a1);
        }
        semb[tid] = fmaxf(a0 + a1, 0.f);
    }
    __syncthreads();

    if (tid < K_) {
        const float* wW = warp_W + tid * E_;
        const float* oW = off_W + tid * E_;
        float aw = warp_b[tid];
        float ao = off_b[tid];
        #pragma unroll
        for (int e = 0; e < E_; ++e) {
            float em = semb[e];
            aw = fmaf(wW[e], em, aw);
            ao = fmaf(oW[e], em, ao);
        }
        const int bk = b * K_ + tid;
        g_warp[bk] = aw;
        g_off[bk]  = ao;
        out_warp[bk] = aw;
        out_off[bk]  = ao;
    }
}

// ---------------------------------------------------------------------------
// Stage 3: warped output. blockIdx.y = bk, blockIdx.x = 256-t tile.
// Prototype rows for the tile are contiguous (idx monotone, block-uniform w):
// stage once in smem (halves LTS read traffic), then 4 float4/thread with all
// LDS issued before the stores (MLP), plain STG (let L2 absorb writes).
// ---------------------------------------------------------------------------
__global__ __launch_bounds__(256) void warp_kernel(
    const float* __restrict__ proto,   // [K, T, C]
    float4* __restrict__ out)          // [B, K, T, C] as float4
{
    __shared__ float4 sp[(WSEG_ + 2) * 4];     // up to 258 rows x 4 quads

    const int bk = blockIdx.y;
    const int k  = bk & (K_ - 1);
    const float w = g_warp[bk];
    const float o = g_off[bk];
    const int t0 = blockIdx.x * WSEG_;

    // contiguous row range for this tile
    const float idx_lo = fminf(fmaxf((float)t0 - w, 0.f), (float)(T_ - 1));
    const float idx_hi = fminf(fmaxf((float)(t0 + WSEG_ - 1) - w, 0.f), (float)(T_ - 1));
    const int r_lo = (int)floorf(idx_lo);
    const int r_hi = min((int)floorf(idx_hi) + 1, T_ - 1);
    const int n4   = (r_hi - r_lo + 1) * 4;    // <= 1032 float4

    const float4* pk = (const float4*)(proto + (size_t)k * T_ * C_);
    for (int i = threadIdx.x; i < n4; i += 256)
        sp[i] = pk[r_lo * 4 + i];
    __syncthreads();

    const int q  = threadIdx.x & 3;
    const int tl = threadIdx.x >> 2;           // 0..63
    float4* ob = out + ((size_t)bk * T_) * 4;

    int   i0[4], i1[4];
    float fr[4];
    #pragma unroll
    for (int h = 0; h < 4; ++h) {
        const int t = t0 + tl + h * 64;
        float idx = fminf(fmaxf((float)t - w, 0.f), (float)(T_ - 1));
        float i0f = floorf(idx);
        i0[h] = (int)i0f - r_lo;
        i1[h] = min((int)i0f + 1, T_ - 1) - r_lo;
        fr[h] = idx - i0f;
    }

    float4 a[4], c[4];
    #pragma unroll
    for (int h = 0; h < 4; ++h) {
        a[h] = sp[i0[h] * 4 + q];
        c[h] = sp[i1[h] * 4 + q];
    }

    #pragma unroll
    for (int h = 0; h < 4; ++h) {
        const int t = t0 + tl + h * 64;
        const float f = fr[h];
        float4 res;
        res.x = fmaf(f, c[h].x - a[h].x, a[h].x) + o;
        res.y = fmaf(f, c[h].y - a[h].y, a[h].y) + o;
        res.z = fmaf(f, c[h].z - a[h].z, a[h].z) + o;
        res.w = fmaf(f, c[h].w - a[h].w, a[h].w) + o;
        ob[t * 4 + q] = res;
    }
}

extern "C" void kernel_launch(void* const* d_in, const int* in_sizes, int n_in,
                              void* d_out, int out_size) {
    const float* x       = (const float*)d_in[0];
    const float* proto   = (const float*)d_in[1];
    const float* conv_w  = (const float*)d_in[2];
    const float* conv_b  = (const float*)d_in[3];
    const float* lin_w   = (const float*)d_in[4];
    const float* lin_b   = (const float*)d_in[5];
    const float* warp_W  = (const float*)d_in[6];
    const float* warp_b  = (const float*)d_in[7];
    const float* off_W   = (const float*)d_in[8];
    const float* off_b   = (const float*)d_in[9];

    float* out = (float*)d_out;
    const size_t warped_elems = (size_t)B_ * K_ * T_ * C_; // 41,943,040
    float* out_warp = out + warped_elems;
    float* out_off  = out_warp + (size_t)B_ * K_;

    dim3 g1(POOL_, B_);
    conv_pool_kernel<<<g1, 256>>>(x, conv_w, conv_b);

    head_kernel<<<B_, 64>>>(lin_w, lin_b, warp_W, warp_b, off_W, off_b,
                            out_warp, out_off);

    dim3 g3(T_ / WSEG_, B_ * K_);
    warp_kernel<<<g3, 256>>>(proto, (float4*)out);
}